// round 14
// baseline (speedup 1.0000x reference)
#include <cuda_runtime.h>
#include <stdint.h>

// Problem constants (fixed instance: n=5003, K=3, k=1, num_sample=100)
#define NN      5003
#define NSAMPLE 100
#define KSEL    1
#define TPB     512
#define NWARP   (TPB / 32)
#define NITER   10                     // ceil(5003/512)
#define TINYF   1.17549435e-38f
#define VCAP    2560
#define TIECAP  512

// k_prep layout
#define ZBLK   1024
#define CS_X   20
#define CS_Y   16
#define CS_BLOCKS (CS_X * CS_Y)
#define ROWS_PER ((NN + CS_Y - 1) / CS_Y)   // 313
#define LOGZ_B 20

__device__ double g_part[CS_Y][NN];
__device__ float  g_logZ[NN];
__device__ double g_logp;
__device__ unsigned int g_cnt_sel = 0;

// ---------------------------------------------------------------------------
// threefry2x32, key = (0, 42); partitionable: bits = o0 ^ o1 @ ctr (0, i)
// ---------------------------------------------------------------------------
__device__ __forceinline__ uint32_t threefry_bits(uint32_t idx) {
  uint32_t x0 = 0u, x1 = idx;
  const uint32_t ks0 = 0u;
  const uint32_t ks1 = 42u;
  const uint32_t ks2 = 0x1BD11BDAu ^ ks0 ^ ks1;
#define TF_R(r) { x0 += x1; x1 = __funnelshift_l(x1, x1, (r)); x1 ^= x0; }
  x0 += ks0; x1 += ks1;
  TF_R(13) TF_R(15) TF_R(26) TF_R(6)
  x0 += ks1; x1 += ks2 + 1u;
  TF_R(17) TF_R(29) TF_R(16) TF_R(24)
  x0 += ks2; x1 += ks0 + 2u;
  TF_R(13) TF_R(15) TF_R(26) TF_R(6)
  x0 += ks0; x1 += ks1 + 3u;
  TF_R(17) TF_R(29) TF_R(16) TF_R(24)
  x0 += ks1; x1 += ks2 + 4u;
  TF_R(13) TF_R(15) TF_R(26) TF_R(6)
  x0 += ks2; x1 += ks0 + 5u;
#undef TF_R
  return x0 ^ x1;
}

// jax.random.gumbel elementwise — bit-identical to all passing rounds
__device__ __forceinline__ float gumbel_at(uint32_t idx) {
  uint32_t bits = threefry_bits(idx);
  uint32_t fb = (bits >> 9) | 0x3F800000u;
  float f = __uint_as_float(fb) - 1.0f;             // exact
  float u = fmaxf(TINYF, __fadd_rn(f, TINYF));
  return -__logf(-__logf(u));
}

// ---------------------------------------------------------------------------
// k_prep: zero C (DRAM) || colsum partials (MUFU+DRAM) || init, one launch
// ---------------------------------------------------------------------------
__global__ void k_prep(float *__restrict__ out, size_t total,
                       const float *__restrict__ Bk) {
  int bid = blockIdx.x;
  int tid = threadIdx.x;
  if (bid < ZBLK) {
    size_t i = (size_t)bid * blockDim.x + tid;
    size_t stride = (size_t)ZBLK * blockDim.x;
    size_t nv4 = total >> 2;
    float4 *o4 = (float4 *)out;
    float4 z4 = make_float4(0.f, 0.f, 0.f, 0.f);
    for (size_t j = i; j < nv4; j += stride) o4[j] = z4;
    for (size_t j = (nv4 << 2) + i; j < total; j += stride) out[j] = 0.0f;
  } else if (bid < ZBLK + CS_BLOCKS) {
    int cb = bid - ZBLK;
    int cx = cb % CS_X;
    int cy = cb / CS_X;
    int c = cx * 256 + tid;
    if (tid < 256 && c < NN) {
      int r0 = cy * ROWS_PER;
      int r1 = min(r0 + ROWS_PER, NN);
      float a0 = 0.f, a1 = 0.f, a2 = 0.f, a3 = 0.f;
      int r = r0;
      for (; r + 3 < r1; r += 4) {
        a0 += __expf(Bk[(size_t)(r + 0) * NN + c]);
        a1 += __expf(Bk[(size_t)(r + 1) * NN + c]);
        a2 += __expf(Bk[(size_t)(r + 2) * NN + c]);
        a3 += __expf(Bk[(size_t)(r + 3) * NN + c]);
      }
      for (; r < r1; r++) a0 += __expf(Bk[(size_t)r * NN + c]);
      g_part[cy][c] = (double)((a0 + a1) + (a2 + a3));
    }
  } else if (tid == 0) {
    g_logp = 0.0;
    g_cnt_sel = 0;
  }
}

// ---------------------------------------------------------------------------
// k_mid: logZ finalize in blocks [0, LOGZ_B); edge scatter after
// ---------------------------------------------------------------------------
__global__ void k_mid(const int *__restrict__ ei, int ne, float *__restrict__ C) {
  int bid = blockIdx.x;
  int tid = threadIdx.x;
  if (bid < LOGZ_B) {
    int c = bid * 256 + tid;
    if (c < NN) {
      double s = 0.0;
      #pragma unroll
      for (int k = 0; k < CS_Y; k++) s += g_part[k][c];
      g_logZ[c] = logf((float)s);
    }
  } else {
    int e = (bid - LOGZ_B) * 256 + tid;
    if (e < ne) {
      int s = ei[e];
      int d = ei[ne + e];
      C[(size_t)s * NN + d] = 1.0f;
    }
  }
}

// ---------------------------------------------------------------------------
// warp-parallel descending bin select over hist[0..NB): sets *sh_d and
// updates *sh_need to the residual count needed inside the selected bin.
// ---------------------------------------------------------------------------
__device__ __forceinline__ void bin_select(const unsigned int *hist,
                                           int *sh_d, int *sh_need,
                                           int tid, int NB) {
  if (tid < 32) {
    const int per = NB >> 5;
    const int b0 = NB - 1 - per * tid;
    unsigned int psum = 0;
    for (int i = 0; i < per; i++) psum += hist[b0 - i];
    unsigned int pre = psum;
    #pragma unroll
    for (int off = 1; off < 32; off <<= 1) {
      unsigned int v = __shfl_up_sync(0xFFFFFFFFu, pre, off);
      if (tid >= off) pre += v;
    }
    unsigned int excl = pre - psum;
    int need = *sh_need;
    __syncwarp();
    if ((int)excl < need && (int)(excl + psum) >= need) {
      unsigned int cum = excl;
      for (int i = 0; i < per; i++) {
        unsigned int h = hist[b0 - i];
        if ((int)(cum + h) >= need) {
          *sh_d = b0 - i;
          *sh_need = need - (int)cum;
          break;
        }
        cum += h;
      }
    }
  }
  __syncthreads();
}

// ---------------------------------------------------------------------------
// k_select: one block per row. Key build + 2048-bin (11-bit) histogram in one
// pass; compact prefix>=dA into contiguous (vkey,cand); resolve remaining 21
// bits over the compact list; epilogue (flip C, log_p) over the compact list.
// Full-row fallback if the compact list would overflow (exactness guard).
// ---------------------------------------------------------------------------
__global__ __launch_bounds__(TPB) void k_select(const float *__restrict__ Bk,
                                                float *__restrict__ C,
                                                float *__restrict__ out,
                                                size_t total) {
  __shared__ uint32_t keys[NN];
  __shared__ uint32_t vkey[VCAP];
  __shared__ unsigned short cand[VCAP];
  __shared__ unsigned short tiebuf[TIECAP];
  __shared__ unsigned int hist[2048];
  __shared__ double warpsum[NWARP];
  __shared__ int sh_need, sh_d, sh_m, sh_eqn;

  const int r = blockIdx.x;
  const int tid = threadIdx.x;
  const int lane = tid & 31;
  const uint32_t base = (uint32_t)r * (uint32_t)NN;

  #pragma unroll
  for (int i = 0; i < 4; i++) hist[tid + i * TPB] = 0u;
  if (tid == 0) { sh_need = NSAMPLE; sh_m = 0; sh_eqn = 0; }
  __syncthreads();

  // ---- pass 1: build keys + 11-bit histogram (match-aggregated atomics) ----
  #pragma unroll 2
  for (int j = 0; j < NITER; j++) {
    int c = tid + j * TPB;
    unsigned int bin = 0xFFFFu;
    if (c < NN) {
      float b = Bk[base + (uint32_t)c];          // coalesced
      float g = gumbel_at(base + (uint32_t)c);
      float v = __fadd_rn(__fsub_rn(b, g_logZ[c]), g);
      uint32_t fb = __float_as_uint(v);
      fb = (fb & 0x80000000u) ? ~fb : (fb | 0x80000000u);
      keys[c] = fb;
      bin = fb >> 21;
    }
    unsigned int mm = __match_any_sync(0xFFFFFFFFu, bin);
    if ((int)(__ffs(mm) - 1) == lane && bin < 2048u)
      atomicAdd(&hist[bin], __popc(mm));
  }
  __syncthreads();

  bin_select(hist, &sh_d, &sh_need, tid, 2048);
  const uint32_t dA = (uint32_t)sh_d;

  // ---- compaction: all prefix >= dA into contiguous (vkey, cand) ----
  #pragma unroll 2
  for (int j = 0; j < NITER; j++) {
    int c = tid + j * TPB;
    uint32_t kk = (c < NN) ? keys[c] : 0u;
    bool p = (c < NN) && ((kk >> 21) >= dA);
    unsigned int mask = __ballot_sync(0xFFFFFFFFu, p);
    if (mask) {
      int leader = __ffs(mask) - 1;
      int basep = 0;
      if (lane == leader) basep = atomicAdd(&sh_m, __popc(mask));
      basep = __shfl_sync(0xFFFFFFFFu, basep, leader);
      if (p) {
        int pos = basep + __popc(mask & ((1u << lane) - 1u));
        if (pos < VCAP) {
          vkey[pos] = kk;
          cand[pos] = (unsigned short)c;
        }
      }
    }
  }
  // zero hist for the next pass (only 2048 entries)
  __syncthreads();
  #pragma unroll
  for (int i = 0; i < 4; i++) hist[tid + i * TPB] = 0u;
  __syncthreads();

  const int m = sh_m;
  const bool fits = (m <= VCAP);
  uint32_t T;

  if (fits) {
    // ---- level 1: bits [20:10] over compact list ----
    const int miters = (m + TPB - 1) / TPB;
    for (int j = 0; j < miters; j++) {
      int i = tid + j * TPB;
      unsigned int bin = 0xFFFFu;
      if (i < m) {
        uint32_t kk = vkey[i];
        if ((kk >> 21) == dA) bin = (kk >> 10) & 2047u;
      }
      unsigned int mm = __match_any_sync(0xFFFFFFFFu, bin);
      if ((int)(__ffs(mm) - 1) == lane && bin < 2048u)
        atomicAdd(&hist[bin], __popc(mm));
    }
    __syncthreads();
    bin_select(hist, &sh_d, &sh_need, tid, 2048);
    const uint32_t pref21 = (dA << 11) | (uint32_t)sh_d;

    // ---- level 2: bits [9:0] over compact list ----
    #pragma unroll
    for (int i = 0; i < 2; i++) hist[tid + i * TPB] = 0u;
    __syncthreads();
    for (int j = 0; j < miters; j++) {
      int i = tid + j * TPB;
      unsigned int bin = 0xFFFFu;
      if (i < m) {
        uint32_t kk = vkey[i];
        if ((kk >> 10) == pref21) bin = kk & 1023u;
      }
      unsigned int mm = __match_any_sync(0xFFFFFFFFu, bin);
      if ((int)(__ffs(mm) - 1) == lane && bin < 1024u)
        atomicAdd(&hist[bin], __popc(mm));
    }
    __syncthreads();
    bin_select(hist, &sh_d, &sh_need, tid, 1024);
    T = (pref21 << 10) | (uint32_t)sh_d;
  } else {
    // ---- fallback (never expected): full-row prefix-filtered passes ----
    const uint32_t shifted = dA;   // 11-bit prefix
    for (int j = 0; j < NITER; j++) {
      int c = tid + j * TPB;
      unsigned int bin = 0xFFFFu;
      if (c < NN) {
        uint32_t kk = keys[c];
        if ((kk >> 21) == shifted) bin = (kk >> 10) & 2047u;
      }
      unsigned int mm = __match_any_sync(0xFFFFFFFFu, bin);
      if ((int)(__ffs(mm) - 1) == lane && bin < 2048u)
        atomicAdd(&hist[bin], __popc(mm));
    }
    __syncthreads();
    bin_select(hist, &sh_d, &sh_need, tid, 2048);
    const uint32_t pref21 = (dA << 11) | (uint32_t)sh_d;

    #pragma unroll
    for (int i = 0; i < 2; i++) hist[tid + i * TPB] = 0u;
    __syncthreads();
    for (int j = 0; j < NITER; j++) {
      int c = tid + j * TPB;
      unsigned int bin = 0xFFFFu;
      if (c < NN) {
        uint32_t kk = keys[c];
        if ((kk >> 10) == pref21) bin = kk & 1023u;
      }
      unsigned int mm = __match_any_sync(0xFFFFFFFFu, bin);
      if ((int)(__ffs(mm) - 1) == lane && bin < 1024u)
        atomicAdd(&hist[bin], __popc(mm));
    }
    __syncthreads();
    bin_select(hist, &sh_d, &sh_need, tid, 1024);
    T = (pref21 << 10) | (uint32_t)sh_d;
  }

  const int need_eq = sh_need;   // number of key==T elements to take

  // ---- epilogue: flip C, accumulate log_p ----
  double local = 0.0;
  if (fits) {
    for (int i = tid; i < m; i += TPB) {
      uint32_t kk = vkey[i];
      if (kk > T) {
        int c = cand[i];
        size_t idx = (size_t)c * NN + r;   // M[s=c, i=r] -> flip C[c, r]
        local += (double)Bk[idx];          // vals[i,j] = Bk[S[i,j], i]
        C[idx] = 1.0f - C[idx];
      } else if (kk == T) {
        int p = atomicAdd(&sh_eqn, 1);
        if (p < TIECAP) tiebuf[p] = cand[i];
      }
    }
  } else {
    for (int c = tid; c < NN; c += TPB) {
      uint32_t kk = keys[c];
      if (kk > T) {
        size_t idx = (size_t)c * NN + r;
        local += (double)Bk[idx];
        C[idx] = 1.0f - C[idx];
      } else if (kk == T) {
        int p = atomicAdd(&sh_eqn, 1);
        if (p < TIECAP) tiebuf[p] = (unsigned short)c;
      }
    }
  }
  __syncthreads();
  const int neq = min(sh_eqn, TIECAP);   // >= need_eq >= 1 (ties tiny in practice)
  for (int i = tid; i < neq; i += TPB) {
    int ci = tiebuf[i];
    int rank = 0;
    for (int jj = 0; jj < neq; jj++) rank += (tiebuf[jj] < ci);
    if (rank < need_eq) {                // lowest-index-first tie break
      size_t idx = (size_t)ci * NN + r;
      local += (double)Bk[idx];
      C[idx] = 1.0f - C[idx];
    }
  }

  // block reduce (double), one global atomic; last block writes the scalar
  #pragma unroll
  for (int off = 16; off; off >>= 1)
    local += __shfl_down_sync(0xFFFFFFFFu, local, off);
  if (lane == 0) warpsum[tid >> 5] = local;
  __syncthreads();
  if (tid == 0) {
    double t = 0.0;
    #pragma unroll
    for (int w = 0; w < NWARP; w++) t += warpsum[w];
    atomicAdd(&g_logp, t - (double)g_logZ[r]);
    __threadfence();
    unsigned done = atomicAdd(&g_cnt_sel, 1u);
    if (done == (unsigned)(gridDim.x - 1)) {
      double lp = atomicAdd(&g_logp, 0.0);     // atomic read
      size_t pos = (size_t)NN * NN;
      if (pos < total) out[pos] = (float)lp;
      g_logp = 0.0;                            // reset for graph replay
      g_cnt_sel = 0;
    }
  }
}

// ---------------------------------------------------------------------------
// Launch — 3 launches, serial on the capture stream
// ---------------------------------------------------------------------------
extern "C" void kernel_launch(void *const *d_in, const int *in_sizes, int n_in,
                              void *d_out, int out_size) {
  const int   *ei = (const int *)d_in[0];     // edge_index [2, n_edges] int32
  const float *B  = (const float *)d_in[1];   // B [K, n, n] float32
  const int ne = in_sizes[0] / 2;
  const float *Bk = B + (size_t)KSEL * NN * NN;
  float *out = (float *)d_out;
  const size_t total = (size_t)out_size;

  k_prep<<<ZBLK + CS_BLOCKS + 1, 256>>>(out, total, Bk);
  const int eb = (ne + 255) / 256;
  k_mid<<<LOGZ_B + eb, 256>>>(ei, ne, out);
  k_select<<<NN, TPB>>>(Bk, out, out, total);
}

// round 17
// speedup vs baseline: 1.2311x; 1.2311x over previous
#include <cuda_runtime.h>
#include <stdint.h>
#include <math.h>

// Problem constants (fixed instance: n=5003, K=3, k=1, num_sample=100)
#define NN      5003
#define NSAMPLE 100
#define KSEL    1
#define TPB     512
#define NWARP   (TPB / 32)
#define NITER   10                     // ceil(5003/512)
#define TINYF   1.17549435e-38f
#define VCAP    2560
#define TIECAP  512

// k_prep layout
#define ZBLK   1024
#define CS_X   20
#define CS_Y   16
#define CS_BLOCKS (CS_X * CS_Y)
#define ROWS_PER ((NN + CS_Y - 1) / CS_Y)   // 313
#define LOGZ_B 20

// survivor-filter witness threshold in 23-bit mantissa space (~ g >= 3.0)
#define U_B 7981470u

__device__ double g_part[CS_Y][NN];
__device__ float  g_logZ[NN];
__device__ int    g_lzmin_i, g_lzmax_i;   // float bits; logZ>0 so int order ok
__device__ double g_logp;
__device__ unsigned int g_cnt_sel = 0;

// ---------------------------------------------------------------------------
// threefry2x32, key = (0, 42); partitionable: bits = o0 ^ o1 @ ctr (0, i)
// ---------------------------------------------------------------------------
__device__ __forceinline__ uint32_t threefry_bits(uint32_t idx) {
  uint32_t x0 = 0u, x1 = idx;
  const uint32_t ks0 = 0u;
  const uint32_t ks1 = 42u;
  const uint32_t ks2 = 0x1BD11BDAu ^ ks0 ^ ks1;
#define TF_R(r) { x0 += x1; x1 = __funnelshift_l(x1, x1, (r)); x1 ^= x0; }
  x0 += ks0; x1 += ks1;
  TF_R(13) TF_R(15) TF_R(26) TF_R(6)
  x0 += ks1; x1 += ks2 + 1u;
  TF_R(17) TF_R(29) TF_R(16) TF_R(24)
  x0 += ks2; x1 += ks0 + 2u;
  TF_R(13) TF_R(15) TF_R(26) TF_R(6)
  x0 += ks0; x1 += ks1 + 3u;
  TF_R(17) TF_R(29) TF_R(16) TF_R(24)
  x0 += ks1; x1 += ks2 + 4u;
  TF_R(13) TF_R(15) TF_R(26) TF_R(6)
  x0 += ks2; x1 += ks0 + 5u;
#undef TF_R
  return x0 ^ x1;
}

// gumbel from 23-bit mantissa — bit-identical to all passing rounds
__device__ __forceinline__ float gumbel_from_mant(uint32_t mant) {
  uint32_t fb = mant | 0x3F800000u;
  float f = __uint_as_float(fb) - 1.0f;             // exact
  float u = fmaxf(TINYF, __fadd_rn(f, TINYF));
  return -__logf(-__logf(u));
}

// order-preserving float->uint key
__device__ __forceinline__ uint32_t key_of(float v) {
  uint32_t fb = __float_as_uint(v);
  return (fb & 0x80000000u) ? ~fb : (fb | 0x80000000u);
}

// ---------------------------------------------------------------------------
// k_prep: zero C (DRAM) || colsum partials (MUFU+DRAM) || init, one launch
// ---------------------------------------------------------------------------
__global__ void k_prep(float *__restrict__ out, size_t total,
                       const float *__restrict__ Bk) {
  int bid = blockIdx.x;
  int tid = threadIdx.x;
  if (bid < ZBLK) {
    size_t i = (size_t)bid * blockDim.x + tid;
    size_t stride = (size_t)ZBLK * blockDim.x;
    size_t nv4 = total >> 2;
    float4 *o4 = (float4 *)out;
    float4 z4 = make_float4(0.f, 0.f, 0.f, 0.f);
    for (size_t j = i; j < nv4; j += stride) o4[j] = z4;
    for (size_t j = (nv4 << 2) + i; j < total; j += stride) out[j] = 0.0f;
  } else if (bid < ZBLK + CS_BLOCKS) {
    int cb = bid - ZBLK;
    int cx = cb % CS_X;
    int cy = cb / CS_X;
    int c = cx * 256 + tid;
    if (tid < 256 && c < NN) {
      int r0 = cy * ROWS_PER;
      int r1 = min(r0 + ROWS_PER, NN);
      float a0 = 0.f, a1 = 0.f, a2 = 0.f, a3 = 0.f;
      int r = r0;
      for (; r + 3 < r1; r += 4) {
        a0 += __expf(Bk[(size_t)(r + 0) * NN + c]);
        a1 += __expf(Bk[(size_t)(r + 1) * NN + c]);
        a2 += __expf(Bk[(size_t)(r + 2) * NN + c]);
        a3 += __expf(Bk[(size_t)(r + 3) * NN + c]);
      }
      for (; r < r1; r++) a0 += __expf(Bk[(size_t)r * NN + c]);
      g_part[cy][c] = (double)((a0 + a1) + (a2 + a3));
    }
  } else if (tid == 0) {
    g_logp = 0.0;
    g_cnt_sel = 0;
    g_lzmin_i = 0x7F800000;    // +inf
    g_lzmax_i = 0;
  }
}

// ---------------------------------------------------------------------------
// k_mid: logZ finalize (+min/max) in blocks [0, LOGZ_B); edge scatter after
// ---------------------------------------------------------------------------
__global__ void k_mid(const int *__restrict__ ei, int ne, float *__restrict__ C) {
  int bid = blockIdx.x;
  int tid = threadIdx.x;
  if (bid < LOGZ_B) {
    int c = bid * 256 + tid;
    float lmin = 1e30f, lmax = -1e30f;
    if (c < NN) {
      double s = 0.0;
      #pragma unroll
      for (int k = 0; k < CS_Y; k++) s += g_part[k][c];
      float lz = logf((float)s);
      g_logZ[c] = lz;
      lmin = lz; lmax = lz;
    }
    #pragma unroll
    for (int off = 16; off; off >>= 1) {
      lmin = fminf(lmin, __shfl_down_sync(0xFFFFFFFFu, lmin, off));
      lmax = fmaxf(lmax, __shfl_down_sync(0xFFFFFFFFu, lmax, off));
    }
    if ((tid & 31) == 0) {
      atomicMin(&g_lzmin_i, __float_as_int(lmin));
      atomicMax(&g_lzmax_i, __float_as_int(lmax));
    }
  } else {
    int e = (bid - LOGZ_B) * 256 + tid;
    if (e < ne) {
      int s = ei[e];
      int d = ei[ne + e];
      C[(size_t)s * NN + d] = 1.0f;
    }
  }
}

// warp-parallel descending bin select over hist[256]: sets *sh_d, updates *sh_need
__device__ __forceinline__ void bin_select(const unsigned int *hist,
                                           int *sh_d, int *sh_need, int tid) {
  if (tid < 32) {
    const int b0 = 255 - 8 * tid;
    unsigned int psum = 0;
    #pragma unroll
    for (int i = 0; i < 8; i++) psum += hist[b0 - i];
    unsigned int pre = psum;
    #pragma unroll
    for (int off = 1; off < 32; off <<= 1) {
      unsigned int v = __shfl_up_sync(0xFFFFFFFFu, pre, off);
      if (tid >= off) pre += v;
    }
    unsigned int excl = pre - psum;
    int need = *sh_need;
    __syncwarp();
    if ((int)excl < need && (int)(excl + psum) >= need) {
      unsigned int cum = excl;
      #pragma unroll
      for (int i = 0; i < 8; i++) {
        unsigned int h = hist[b0 - i];
        if ((int)(cum + h) >= need) {
          *sh_d = b0 - i;
          *sh_need = need - (int)cum;
          break;
        }
        cum += h;
      }
    }
  }
  __syncthreads();
}

// ---------------------------------------------------------------------------
// k_select: one block per row.
//  pass 1: threefry (registers) + coalesced Bk read + store (b-logZ) + witness
//  cut:    provable mantissa bound -> ~10-15% survivors
//  pass 2: survivors only get logs; compact into (vkey, cand)
//  radix:  4 x 8-bit passes over ~700-entry compact list; epilogue on it
//  fallback (cutm==0 or overflow): full-row keys + full radix (exactness)
// ---------------------------------------------------------------------------
__global__ __launch_bounds__(TPB) void k_select(const float *__restrict__ Bk,
                                                float *__restrict__ C,
                                                float *__restrict__ out,
                                                size_t total) {
  __shared__ uint32_t pkey[NN];              // b-logZ bits; full keys in fallback
  __shared__ uint32_t vkey[VCAP];
  __shared__ unsigned short cand[VCAP];
  __shared__ unsigned short tiebuf[TIECAP];
  __shared__ unsigned int hist[256];
  __shared__ double warpsum[NWARP];
  __shared__ int sh_cnt, sh_m, sh_need, sh_d, sh_eqn;
  __shared__ uint32_t sh_cutm, sh_pref;

  const int r = blockIdx.x;
  const int tid = threadIdx.x;
  const int lane = tid & 31;
  const uint32_t base = (uint32_t)r * (uint32_t)NN;

  if (tid == 0) {
    sh_cnt = 0; sh_m = 0; sh_eqn = 0;
    sh_need = NSAMPLE; sh_pref = 0u;
  }
  __syncthreads();

  // ---- pass 1: threefry to registers, partial key to smem, witness count ----
  uint32_t bb[NITER];
  unsigned cnt = 0;
  #pragma unroll 2
  for (int j = 0; j < NITER; j++) {
    int c = tid + j * TPB;
    bb[j] = threefry_bits(base + (uint32_t)c);          // harmless past NN
    if (c < NN) {
      float b = Bk[base + (uint32_t)c];                 // coalesced
      pkey[c] = __float_as_uint(__fsub_rn(b, g_logZ[c]));
      cnt += (unsigned)((bb[j] >> 9) >= U_B);
    }
  }
  cnt = __reduce_add_sync(0xFFFFFFFFu, cnt);
  if (lane == 0) atomicAdd(&sh_cnt, (int)cnt);
  __syncthreads();

  // ---- conservative mantissa cut (thread 0) — validated in R3/R5 ----
  if (tid == 0) {
    uint32_t cutm = 0;
    if (sh_cnt >= NSAMPLE) {
      float gke = gumbel_from_mant(U_B);      // >=100 elements have g >= gke
      float lzmin = __int_as_float(g_lzmin_i);
      float lzmax = __int_as_float(g_lzmax_i);
      float gcut = gke - (1.0f + (lzmax - lzmin) + 1e-3f);
      double uc = exp(-exp(-(double)gcut));
      double cm = floor(uc * 8388608.0) - 256.0;
      cutm = (cm < 1.0) ? 0u : (uint32_t)cm;
    }
    sh_cutm = cutm;                           // 0 -> fallback full path
  }
  __syncthreads();
  const uint32_t cutm = sh_cutm;

  // ---- pass 2: survivor compaction; logs only for survivors ----
  if (cutm != 0) {
    #pragma unroll 2
    for (int j = 0; j < NITER; j++) {
      int c = tid + j * TPB;
      uint32_t bu = bb[j] >> 9;
      bool p = (c < NN) && (bu >= cutm);
      unsigned mask = __ballot_sync(0xFFFFFFFFu, p);
      if (mask) {
        int leader = __ffs(mask) - 1;
        int basep = 0;
        if (lane == leader) basep = atomicAdd(&sh_m, __popc(mask));
        basep = __shfl_sync(0xFFFFFFFFu, basep, leader);
        if (p) {
          int pos = basep + __popc(mask & ((1u << lane) - 1u));
          if (pos < VCAP) {
            float bl = __uint_as_float(pkey[c]);
            float g = gumbel_from_mant(bu);
            float v = __fadd_rn(bl, g);       // same rounding chain as always
            vkey[pos] = key_of(v);
            cand[pos] = (unsigned short)c;
          }
        }
      }
    }
  }
  __syncthreads();

  const int m = sh_m;
  const bool fits = (cutm != 0) && (m <= VCAP);
  uint32_t T;

  if (fits) {
    // ---- radix: 4 x 8-bit passes over compact list ----
    const int miters = (m + TPB - 1) / TPB;
    for (int shift = 24; shift >= 0; shift -= 8) {
      if (tid < 256) hist[tid] = 0u;
      __syncthreads();
      uint32_t pref = sh_pref;
      int hs = shift + 8;
      for (int j = 0; j < miters; j++) {
        int i = tid + j * TPB;
        unsigned int bin = 0xFFFFu;
        if (i < m) {
          uint32_t kk = vkey[i];
          if (hs >= 32 || (kk >> hs) == (pref >> hs))
            bin = (kk >> shift) & 255u;
        }
        unsigned int mmk = __match_any_sync(0xFFFFFFFFu, bin);
        if ((int)(__ffs(mmk) - 1) == lane && bin < 256u)
          atomicAdd(&hist[bin], __popc(mmk));
      }
      __syncthreads();
      bin_select(hist, &sh_d, &sh_need, tid);
      if (tid == 0) sh_pref |= ((uint32_t)sh_d << shift);
      __syncthreads();
    }
    T = sh_pref;
  } else {
    // ---- fallback: build full keys in place, full-row radix ----
    #pragma unroll 2
    for (int j = 0; j < NITER; j++) {
      int c = tid + j * TPB;
      if (c < NN) {
        float bl = __uint_as_float(pkey[c]);
        float g = gumbel_from_mant(bb[j] >> 9);
        pkey[c] = key_of(__fadd_rn(bl, g));
      }
    }
    __syncthreads();
    for (int shift = 24; shift >= 0; shift -= 8) {
      if (tid < 256) hist[tid] = 0u;
      __syncthreads();
      uint32_t pref = sh_pref;
      int hs = shift + 8;
      for (int j = 0; j < NITER; j++) {
        int c = tid + j * TPB;
        unsigned int bin = 0xFFFFu;
        if (c < NN) {
          uint32_t kk = pkey[c];
          if (hs >= 32 || (kk >> hs) == (pref >> hs))
            bin = (kk >> shift) & 255u;
        }
        unsigned int mmk = __match_any_sync(0xFFFFFFFFu, bin);
        if ((int)(__ffs(mmk) - 1) == lane && bin < 256u)
          atomicAdd(&hist[bin], __popc(mmk));
      }
      __syncthreads();
      bin_select(hist, &sh_d, &sh_need, tid);
      if (tid == 0) sh_pref |= ((uint32_t)sh_d << shift);
      __syncthreads();
    }
    T = sh_pref;
  }

  const int need_eq = sh_need;   // number of key==T elements to take

  // ---- epilogue: flip C, accumulate log_p ----
  double local = 0.0;
  if (fits) {
    for (int i = tid; i < m; i += TPB) {
      uint32_t kk = vkey[i];
      if (kk > T) {
        int c = cand[i];
        size_t idx = (size_t)c * NN + r;   // M[s=c, i=r] -> flip C[c, r]
        local += (double)Bk[idx];          // vals[i,j] = Bk[S[i,j], i]
        C[idx] = 1.0f - C[idx];
      } else if (kk == T) {
        int p = atomicAdd(&sh_eqn, 1);
        if (p < TIECAP) tiebuf[p] = cand[i];
      }
    }
  } else {
    for (int c = tid; c < NN; c += TPB) {
      uint32_t kk = pkey[c];
      if (kk > T) {
        size_t idx = (size_t)c * NN + r;
        local += (double)Bk[idx];
        C[idx] = 1.0f - C[idx];
      } else if (kk == T) {
        int p = atomicAdd(&sh_eqn, 1);
        if (p < TIECAP) tiebuf[p] = (unsigned short)c;
      }
    }
  }
  __syncthreads();
  const int neq = min(sh_eqn, TIECAP);   // >= need_eq >= 1
  for (int i = tid; i < neq; i += TPB) {
    int ci = tiebuf[i];
    int rank = 0;
    for (int jj = 0; jj < neq; jj++) rank += (tiebuf[jj] < ci);
    if (rank < need_eq) {                // lowest-index-first tie break
      size_t idx = (size_t)ci * NN + r;
      local += (double)Bk[idx];
      C[idx] = 1.0f - C[idx];
    }
  }

  // block reduce (double), one global atomic; last block writes the scalar
  #pragma unroll
  for (int off = 16; off; off >>= 1)
    local += __shfl_down_sync(0xFFFFFFFFu, local, off);
  if (lane == 0) warpsum[tid >> 5] = local;
  __syncthreads();
  if (tid == 0) {
    double t = 0.0;
    #pragma unroll
    for (int w = 0; w < NWARP; w++) t += warpsum[w];
    atomicAdd(&g_logp, t - (double)g_logZ[r]);
    __threadfence();
    unsigned done = atomicAdd(&g_cnt_sel, 1u);
    if (done == (unsigned)(gridDim.x - 1)) {
      double lp = atomicAdd(&g_logp, 0.0);     // atomic read
      size_t pos = (size_t)NN * NN;
      if (pos < total) out[pos] = (float)lp;
      g_logp = 0.0;                            // reset for graph replay
      g_cnt_sel = 0;
    }
  }
}

// ---------------------------------------------------------------------------
// Launch — 3 launches, serial on the capture stream
// ---------------------------------------------------------------------------
extern "C" void kernel_launch(void *const *d_in, const int *in_sizes, int n_in,
                              void *d_out, int out_size) {
  const int   *ei = (const int *)d_in[0];     // edge_index [2, n_edges] int32
  const float *B  = (const float *)d_in[1];   // B [K, n, n] float32
  const int ne = in_sizes[0] / 2;
  const float *Bk = B + (size_t)KSEL * NN * NN;
  float *out = (float *)d_out;
  const size_t total = (size_t)out_size;

  k_prep<<<ZBLK + CS_BLOCKS + 1, 256>>>(out, total, Bk);
  const int eb = (ne + 255) / 256;
  k_mid<<<LOGZ_B + eb, 256>>>(ei, ne, out);
  k_select<<<NN, TPB>>>(Bk, out, out, total);
}